// round 1
// baseline (speedup 1.0000x reference)
#include <cuda_runtime.h>
#include <math.h>

// Problem constants (B=2, S=2048 -> T=4096 tokens)
namespace {
constexpr int TT = 4096;   // tokens
constexpr int DD = 1024;   // model dim
constexpr int EE = 8;      // experts
constexpr int FF = 4096;   // ffn dim
}

// ---------------- device scratch (no runtime allocation allowed) -----------
__device__ int   g_expert_id[TT];
__device__ int   g_counts[EE];
__device__ int   g_offsets[EE];
__device__ int   g_cursor[EE];
__device__ int   g_perm[TT];                    // perm[p] = token, grouped by expert
__device__ float g_h[(size_t)TT * FF];          // hidden activations (64 MB)

// ---------------- tiny bookkeeping kernels --------------------------------
__global__ void moe_init() {
    if (threadIdx.x < EE) g_counts[threadIdx.x] = 0;
}

// Router: one warp per token. logits[t][e] = sum_k x[t][k]*gate_w[e][k]
__global__ void moe_router(const float* __restrict__ x, const float* __restrict__ gw) {
    __shared__ float sg[EE * DD];   // 32 KB
    for (int i = threadIdx.x; i < EE * DD; i += blockDim.x) sg[i] = gw[i];
    __syncthreads();

    const int warp  = threadIdx.x >> 5;
    const int lane  = threadIdx.x & 31;
    const int token = blockIdx.x * 8 + warp;

    const float* xr = x + (size_t)token * DD;
    float acc[EE];
    #pragma unroll
    for (int e = 0; e < EE; e++) acc[e] = 0.f;

    for (int k = lane; k < DD; k += 32) {
        const float xv = xr[k];
        #pragma unroll
        for (int e = 0; e < EE; e++) acc[e] = fmaf(xv, sg[e * DD + k], acc[e]);
    }
    #pragma unroll
    for (int e = 0; e < EE; e++) {
        #pragma unroll
        for (int off = 16; off > 0; off >>= 1)
            acc[e] += __shfl_xor_sync(0xffffffffu, acc[e], off);
    }
    if (lane == 0) {
        int best = 0; float bv = acc[0];
        #pragma unroll
        for (int e = 1; e < EE; e++) {        // strict '>' keeps first max (jnp.argmax)
            if (acc[e] > bv) { bv = acc[e]; best = e; }
        }
        g_expert_id[token] = best;
        atomicAdd(&g_counts[best], 1);
    }
}

__global__ void moe_scan() {
    if (threadIdx.x == 0) {
        int s = 0;
        for (int e = 0; e < EE; e++) { g_offsets[e] = s; g_cursor[e] = s; s += g_counts[e]; }
    }
}

__global__ void moe_scatter() {
    const int t = blockIdx.x * blockDim.x + threadIdx.x;
    if (t >= TT) return;
    const int e = g_expert_id[t];
    const int p = atomicAdd(&g_cursor[e], 1);
    g_perm[p] = t;
}

// ---------------- grouped SGEMM: 128x128 tile, 8x8/thread, TK=16 ----------
// PHASE 1: A = gathered x rows (perm), C = gelu(A@w1[e]) -> g_h
// PHASE 2: A = g_h rows (dense),      C = A@w2[e] scattered to Out rows
template<int KDIM, int NDIM, int PHASE>
__global__ __launch_bounds__(256, 2) void moe_gemm(const float* __restrict__ Xin,
                                                   const float* __restrict__ W,
                                                   float* __restrict__ Out) {
    const int e   = blockIdx.z;
    const int cnt = g_counts[e];
    const int m0  = blockIdx.x * 128;
    if (m0 >= cnt) return;                      // oversized grid: cheap early exit
    const int off = g_offsets[e];
    const int n0  = blockIdx.y * 128;
    const float* B = W + (size_t)e * KDIM * NDIM;

    __shared__ float As[16][128];
    __shared__ float Bs[16][128];

    const int tid = threadIdx.x;

    // A-tile load mapping: rows tid/4 and tid/4+64, k-chunk (tid&3)*4 (float4)
    const int la_r = tid >> 2;
    const int la_k = (tid & 3) * 4;
    const int gr0  = m0 + la_r;
    const int gr1  = gr0 + 64;
    const bool v0  = gr0 < cnt;
    const bool v1  = gr1 < cnt;
    const float* arow0;
    const float* arow1;
    if (PHASE == 1) {
        arow0 = v0 ? (Xin + (size_t)g_perm[off + gr0] * KDIM) : Xin;
        arow1 = v1 ? (Xin + (size_t)g_perm[off + gr1] * KDIM) : Xin;
    } else {
        arow0 = g_h + (size_t)(off + (v0 ? gr0 : 0)) * KDIM;
        arow1 = g_h + (size_t)(off + (v1 ? gr1 : 0)) * KDIM;
    }

    // B-tile load mapping: k rows tid/32 and tid/32+8, 4 cols (tid&31)*4 (float4)
    const int lb_k = tid >> 5;
    const int lb_n = (tid & 31) * 4;

    const int r0 = (tid >> 4) * 8;   // thread output rows within tile
    const int c0 = (tid & 15) * 8;   // thread output cols within tile

    float acc[8][8];
    #pragma unroll
    for (int i = 0; i < 8; i++)
        #pragma unroll
        for (int j = 0; j < 8; j++) acc[i][j] = 0.f;

    for (int k0 = 0; k0 < KDIM; k0 += 16) {
        const float4 a0 = v0 ? *(const float4*)(arow0 + k0 + la_k) : make_float4(0.f, 0.f, 0.f, 0.f);
        const float4 a1 = v1 ? *(const float4*)(arow1 + k0 + la_k) : make_float4(0.f, 0.f, 0.f, 0.f);
        const float4 b0 = *(const float4*)(B + (size_t)(k0 + lb_k)     * NDIM + n0 + lb_n);
        const float4 b1 = *(const float4*)(B + (size_t)(k0 + lb_k + 8) * NDIM + n0 + lb_n);

        __syncthreads();   // previous tile's compute finished
        As[la_k + 0][la_r] = a0.x; As[la_k + 1][la_r] = a0.y;
        As[la_k + 2][la_r] = a0.z; As[la_k + 3][la_r] = a0.w;
        As[la_k + 0][la_r + 64] = a1.x; As[la_k + 1][la_r + 64] = a1.y;
        As[la_k + 2][la_r + 64] = a1.z; As[la_k + 3][la_r + 64] = a1.w;
        *(float4*)&Bs[lb_k][lb_n]     = b0;
        *(float4*)&Bs[lb_k + 8][lb_n] = b1;
        __syncthreads();

        #pragma unroll
        for (int kk = 0; kk < 16; kk++) {
            const float4 ra0 = *(const float4*)&As[kk][r0];
            const float4 ra1 = *(const float4*)&As[kk][r0 + 4];
            const float4 rb0 = *(const float4*)&Bs[kk][c0];
            const float4 rb1 = *(const float4*)&Bs[kk][c0 + 4];
            const float ra[8] = {ra0.x, ra0.y, ra0.z, ra0.w, ra1.x, ra1.y, ra1.z, ra1.w};
            const float rb[8] = {rb0.x, rb0.y, rb0.z, rb0.w, rb1.x, rb1.y, rb1.z, rb1.w};
            #pragma unroll
            for (int i = 0; i < 8; i++)
                #pragma unroll
                for (int j = 0; j < 8; j++)
                    acc[i][j] = fmaf(ra[i], rb[j], acc[i][j]);
        }
    }

    // epilogue
    #pragma unroll
    for (int i = 0; i < 8; i++) {
        const int gr = m0 + r0 + i;
        if (gr >= cnt) continue;
        if (PHASE == 1) {
            float* dst = g_h + (size_t)(off + gr) * FF + n0 + c0;
            float v[8];
            #pragma unroll
            for (int j = 0; j < 8; j++) {
                const float t = acc[i][j];
                v[j] = 0.5f * t * (1.0f + erff(t * 0.70710678118654752f));  // exact GELU
            }
            *(float4*)(dst)     = make_float4(v[0], v[1], v[2], v[3]);
            *(float4*)(dst + 4) = make_float4(v[4], v[5], v[6], v[7]);
        } else {
            const int token = g_perm[off + gr];
            float* dst = Out + (size_t)token * DD + n0 + c0;
            *(float4*)(dst)     = make_float4(acc[i][0], acc[i][1], acc[i][2], acc[i][3]);
            *(float4*)(dst + 4) = make_float4(acc[i][4], acc[i][5], acc[i][6], acc[i][7]);
        }
    }
}

// ---------------- launch ---------------------------------------------------
extern "C" void kernel_launch(void* const* d_in, const int* in_sizes, int n_in,
                              void* d_out, int out_size) {
    (void)in_sizes; (void)n_in; (void)out_size;
    const float* x  = (const float*)d_in[0];   // (2,2048,1024) -> (4096,1024)
    const float* gw = (const float*)d_in[1];   // (8,1024)
    const float* w1 = (const float*)d_in[2];   // (8,1024,4096)
    const float* w2 = (const float*)d_in[3];   // (8,4096,1024)
    float* out = (float*)d_out;                // (4096,1024)

    moe_init<<<1, 32>>>();
    moe_router<<<TT / 8, 256>>>(x, gw);
    moe_scan<<<1, 1>>>();
    moe_scatter<<<TT / 256, 256>>>();

    // GEMM1: M<=cnt_e, N=F, K=D. Oversized m-grid (32 tiles covers worst case T rows).
    moe_gemm<DD, FF, 1><<<dim3(32, FF / 128, EE), 256>>>(x, w1, nullptr);
    // GEMM2: M<=cnt_e, N=D, K=F.
    moe_gemm<FF, DD, 2><<<dim3(32, DD / 128, EE), 256>>>(nullptr, w2, out);
}